// round 13
// baseline (speedup 1.0000x reference)
#include <cuda_runtime.h>
#include <math.h>

#define B_  64
#define T_  2048
#define IN_ 128
#define H_  256
#define M_  (B_ * T_)

typedef unsigned long long ull;

// ---------------- scratch ----------------
__device__ float g_xp[(size_t)B_ * T_ * H_];    // reused for xp0 then xp1
__device__ float g_h1[(size_t)B_ * T_ * H_];    // layer-0 hidden states
__device__ float g_h2last[(size_t)B_ * H_];     // h2[:, T-1, :]

// ---------------- packed fp32x2 helpers ----------------
__device__ __forceinline__ void fma2(ull &d, ull a, ull b) {
    asm("fma.rn.f32x2 %0, %1, %2, %0;" : "+l"(d) : "l"(a), "l"(b));
}
__device__ __forceinline__ void add2(ull &d, ull a, ull b) {
    asm("add.rn.f32x2 %0, %1, %2;" : "=l"(d) : "l"(a), "l"(b));
}
__device__ __forceinline__ ull splat2(float x) {
    ull r; asm("mov.b64 %0, {%1, %1};" : "=l"(r) : "f"(x)); return r;
}
__device__ __forceinline__ float lo2(ull v) { return __uint_as_float((unsigned)(v & 0xffffffffULL)); }
__device__ __forceinline__ float hi2(ull v) { return __uint_as_float((unsigned)(v >> 32)); }

__device__ __forceinline__ float tanh_fast(float s) {
    s = fminf(fmaxf(s, -15.f), 15.f);
    float e; asm("ex2.approx.f32 %0, %1;" : "=f"(e) : "f"(s * 2.885390082f));
    float r; asm("rcp.approx.f32 %0, %1;" : "=f"(r) : "f"(e + 1.f));
    return fmaf(-2.f, r, 1.f);
}

// ---------------- cluster / mbarrier helpers (rec3-proven) ----------------
__device__ __forceinline__ unsigned su32(const void* p) {
    return (unsigned)__cvta_generic_to_shared(p);
}
__device__ __forceinline__ unsigned cta_rank() {
    unsigned r; asm("mov.u32 %0, %%cluster_ctarank;" : "=r"(r)); return r;
}
__device__ __forceinline__ unsigned mapa_u32(unsigned addr, unsigned rank) {
    unsigned r; asm("mapa.shared::cluster.u32 %0, %1, %2;" : "=r"(r) : "r"(addr), "r"(rank));
    return r;
}
__device__ __forceinline__ void mbar_init(unsigned addr, unsigned cnt) {
    asm volatile("mbarrier.init.shared.b64 [%0], %1;" :: "r"(addr), "r"(cnt) : "memory");
}
__device__ __forceinline__ void mbar_expect_tx(unsigned addr, unsigned bytes) {
    asm volatile("mbarrier.arrive.expect_tx.shared.b64 _, [%0], %1;" :: "r"(addr), "r"(bytes) : "memory");
}
__device__ __forceinline__ void mbar_wait_cluster(unsigned addr, unsigned parity) {
    asm volatile(
        "{\n\t.reg .pred P;\n\t"
        "WL_%=:\n\t"
        "mbarrier.try_wait.parity.acquire.cluster.shared::cta.b64 P, [%0], %1, 0x989680;\n\t"
        "@P bra.uni WD_%=;\n\t"
        "bra.uni WL_%=;\n\t"
        "WD_%=:\n\t}"
        :: "r"(addr), "r"(parity) : "memory");
}
__device__ __forceinline__ void st_async_f32(unsigned raddr, float v, unsigned rmbar) {
    asm volatile(
        "st.async.shared::cluster.mbarrier::complete_tx::bytes.b32 [%0], %1, [%2];"
        :: "r"(raddr), "r"(__float_as_uint(v)), "r"(rmbar) : "memory");
}
__device__ __forceinline__ void cluster_sync_() {
    asm volatile("barrier.cluster.arrive.aligned;" ::: "memory");
    asm volatile("barrier.cluster.wait.aligned;" ::: "memory");
}

// 128-k dot: 32 broadcast LDS.128 + 64 fma2
__device__ __forceinline__ float dot128(const float* hb, const ull* wq) {
    ull a0 = 0, a1 = 0, a2 = 0, a3 = 0;
#pragma unroll
    for (int kk = 0; kk < 32; kk += 2) {
        ulonglong2 v0 = *(const ulonglong2*)(hb + kk * 4);
        ulonglong2 v1 = *(const ulonglong2*)(hb + kk * 4 + 4);
        fma2(a0, v0.x, wq[2 * kk]);
        fma2(a1, v0.y, wq[2 * kk + 1]);
        fma2(a2, v1.x, wq[2 * kk + 2]);
        fma2(a3, v1.y, wq[2 * kk + 3]);
    }
    ull s01, s23, s;
    add2(s01, a0, a1); add2(s23, a2, a3); add2(s, s01, s23);
    return lo2(s) + hi2(s);
}

// =====================================================================================
// Phase A / C GEMM (proven): C = A @ W^T + bias0 + bias1
// =====================================================================================
__global__ __launch_bounds__(256, 2)
void gemm_bias_kernel(const float* __restrict__ A, const float* __restrict__ W,
                      const float* __restrict__ bias0, const float* __restrict__ bias1,
                      float* __restrict__ C, int K)
{
    __shared__ float a_sm[16][132];
    __shared__ float b_sm[16][132];
    const int tid = threadIdx.x;
    const int tx = tid & 15, ty = tid >> 4;
    const int mBase = blockIdx.x * 128, nBase = blockIdx.y * 128;

    ull acc[8][4];
#pragma unroll
    for (int i = 0; i < 8; i++)
#pragma unroll
        for (int j = 0; j < 4; j++) acc[i][j] = 0ULL;

    for (int kt = 0; kt < K; kt += 16) {
#pragma unroll
        for (int l = 0; l < 2; l++) {
            int idx = l * 256 + tid, row = idx >> 2, kq = idx & 3;
            float4 v = *(const float4*)(A + (size_t)(mBase + row) * K + kt + kq * 4);
            a_sm[kq * 4 + 0][row] = v.x; a_sm[kq * 4 + 1][row] = v.y;
            a_sm[kq * 4 + 2][row] = v.z; a_sm[kq * 4 + 3][row] = v.w;
        }
#pragma unroll
        for (int l = 0; l < 2; l++) {
            int idx = l * 256 + tid, row = idx >> 2, kq = idx & 3;
            float4 v = *(const float4*)(W + (size_t)(nBase + row) * K + kt + kq * 4);
            b_sm[kq * 4 + 0][row] = v.x; b_sm[kq * 4 + 1][row] = v.y;
            b_sm[kq * 4 + 2][row] = v.z; b_sm[kq * 4 + 3][row] = v.w;
        }
        __syncthreads();
#pragma unroll
        for (int kk = 0; kk < 16; kk++) {
            float4 a0 = *(const float4*)&a_sm[kk][ty * 8];
            float4 a1 = *(const float4*)&a_sm[kk][ty * 8 + 4];
            ulonglong2 b0 = *(const ulonglong2*)&b_sm[kk][tx * 8];
            ulonglong2 b1 = *(const ulonglong2*)&b_sm[kk][tx * 8 + 4];
            float av[8] = {a0.x, a0.y, a0.z, a0.w, a1.x, a1.y, a1.z, a1.w};
#pragma unroll
            for (int i = 0; i < 8; i++) {
                ull s = splat2(av[i]);
                fma2(acc[i][0], s, b0.x); fma2(acc[i][1], s, b0.y);
                fma2(acc[i][2], s, b1.x); fma2(acc[i][3], s, b1.y);
            }
        }
        __syncthreads();
    }
    const int n0 = nBase + tx * 8;
    float bj[8];
#pragma unroll
    for (int j = 0; j < 8; j++) bj[j] = bias0[n0 + j] + bias1[n0 + j];
#pragma unroll
    for (int i = 0; i < 8; i++) {
        int m = mBase + ty * 8 + i;
        float4 o0, o1;
        o0.x = lo2(acc[i][0]) + bj[0]; o0.y = hi2(acc[i][0]) + bj[1];
        o0.z = lo2(acc[i][1]) + bj[2]; o0.w = hi2(acc[i][1]) + bj[3];
        o1.x = lo2(acc[i][2]) + bj[4]; o1.y = hi2(acc[i][2]) + bj[5];
        o1.z = lo2(acc[i][3]) + bj[6]; o1.w = hi2(acc[i][3]) + bj[7];
        *(float4*)(C + (size_t)m * H_ + n0)     = o0;
        *(float4*)(C + (size_t)m * H_ + n0 + 4) = o1;
    }
}

// =====================================================================================
// Recurrence v6: 2 INDEPENDENT rows per 2-CTA pair, software-pipelined.
// 32 pairs = 64 CTAs per layer. Each row has its OWN mbarrier pair and its own
// rec3-identical protocol; the CTA alternates row A / row B inside each iteration,
// so row A's DSMEM flight is airborne during row B's matvec and vice versa.
// Same W slice (128 floats/thread) serves both rows -> no extra weight registers.
// One __syncthreads per iteration (covers both rows' STS).
// =====================================================================================
template<bool STORE_ALL>
__global__ void __cluster_dims__(2, 1, 1) __launch_bounds__(256, 1)
rnn_rec2r(const float* __restrict__ xp, const float* __restrict__ Whh,
          float* __restrict__ hout)
{
    __shared__ __align__(16) float hA[2][264];   // row b0: [buf][own 0..128 | peer@132]
    __shared__ __align__(16) float hB[2][264];   // row b1
    __shared__ __align__(8)  ull mbar[4];        // [0..1]=row A slots, [2..3]=row B slots

    const int tid = threadIdx.x;
    const unsigned rank = cta_rank();
    const unsigned peer = rank ^ 1u;
    const int b0 = 2 * (blockIdx.x >> 1);
    const int w = tid >> 5, l = tid & 31;
    const int half = l & 1;
    const int o = w * 16 + (l >> 1);
    const int o_glob = (int)rank * 128 + o;
    const int kh = half ? (int)peer : (int)rank;

    ull wq[64];
    {
        const ulonglong2* src = (const ulonglong2*)(Whh + (size_t)o_glob * H_ + kh * 128);
#pragma unroll
        for (int j = 0; j < 32; ++j) { ulonglong2 v = src[j]; wq[2 * j] = v.x; wq[2 * j + 1] = v.y; }
    }

    if (tid == 0) {
        mbar_init(su32(&mbar[0]), 1); mbar_init(su32(&mbar[1]), 1);
        mbar_init(su32(&mbar[2]), 1); mbar_init(su32(&mbar[3]), 1);
    }
    for (int i = tid; i < 2 * 264; i += 256) { ((float*)hA)[i] = 0.f; ((float*)hB)[i] = 0.f; }
    __syncthreads();
    cluster_sync_();

    const unsigned myA = su32(&mbar[0]);
    const unsigned myB = su32(&mbar[2]);
    const unsigned peerA = mapa_u32(myA, peer);
    const unsigned peerB = mapa_u32(myB, peer);
    const unsigned peer_hA = mapa_u32(su32(&hA[0][0]), peer);
    const unsigned peer_hB = mapa_u32(su32(&hB[0][0]), peer);
    const int hoff = half ? 132 : 0;

    const size_t xr0 = ((size_t)b0 * T_) * H_ + o_glob;
    const size_t xr1 = ((size_t)(b0 + 1) * T_) * H_ + o_glob;
    float xv0 = 0.f, xv1 = 0.f;
    if (half == 0) { xv0 = __ldg(xp + xr0); xv1 = __ldg(xp + xr1); }

    for (int t = 0; t < T_; ++t) {
        const int cb = t & 1, nb = cb ^ 1;
        const unsigned wpar = (unsigned)((t - 1) >> 1) & 1u;

        // prefetch xp[t+1] for both rows (hidden under the whole iteration)
        float n0 = 0.f, n1 = 0.f;
        if (half == 0 && t + 1 < T_) {
            n0 = __ldg(xp + xr0 + (size_t)(t + 1) * H_);
            n1 = __ldg(xp + xr1 + (size_t)(t + 1) * H_);
        }

        // ---------------- row A ----------------
        if (t > 0) mbar_wait_cluster(myA + (unsigned)nb * 8u, wpar);
        if (tid == 0) mbar_expect_tx(myA + (unsigned)cb * 8u, 512u);
        {
            float p = dot128(&hA[cb][hoff], wq);
            float q = __shfl_down_sync(0xffffffffu, p, 1);
            if (half == 0) {
                float h = tanh_fast(xv0 + p + q);
                hA[nb][o] = h;
                st_async_f32(peer_hA + (unsigned)(nb * 264 + 132 + o) * 4u,
                             h, peerA + (unsigned)cb * 8u);
                if (STORE_ALL)           hout[xr0 + (size_t)t * H_] = h;
                else if (t == T_ - 1)    hout[(size_t)b0 * H_ + o_glob] = h;
            }
        }

        // ---------------- row B (row A's flight is airborne now) ----------------
        if (t > 0) mbar_wait_cluster(myB + (unsigned)nb * 8u, wpar);
        if (tid == 0) mbar_expect_tx(myB + (unsigned)cb * 8u, 512u);
        {
            float p = dot128(&hB[cb][hoff], wq);
            float q = __shfl_down_sync(0xffffffffu, p, 1);
            if (half == 0) {
                float h = tanh_fast(xv1 + p + q);
                hB[nb][o] = h;
                st_async_f32(peer_hB + (unsigned)(nb * 264 + 132 + o) * 4u,
                             h, peerB + (unsigned)cb * 8u);
                if (STORE_ALL)           hout[xr1 + (size_t)t * H_] = h;
                else if (t == T_ - 1)    hout[(size_t)(b0 + 1) * H_ + o_glob] = h;
            }
        }

        __syncthreads();               // both rows' STS visible for next iteration
        xv0 = n0; xv1 = n1;
    }

    // drain final incoming phases (T-1) on both rows before any CTA exits
    mbar_wait_cluster(myA + (unsigned)((T_ - 1) & 1) * 8u, (unsigned)((T_ - 1) >> 1) & 1u);
    mbar_wait_cluster(myB + (unsigned)((T_ - 1) & 1) * 8u, (unsigned)((T_ - 1) >> 1) & 1u);
    cluster_sync_();
}

// =====================================================================================
// Final FC
// =====================================================================================
__global__ void fc_kernel(const float* __restrict__ h2l, const float* __restrict__ Wfc,
                          const float* __restrict__ bfc, float* __restrict__ out)
{
    __shared__ float red[8];
    int b = blockIdx.x, tid = threadIdx.x;
    float v = h2l[(size_t)b * H_ + tid] * Wfc[tid];
#pragma unroll
    for (int o = 16; o > 0; o >>= 1) v += __shfl_down_sync(0xffffffffu, v, o);
    if ((tid & 31) == 0) red[tid >> 5] = v;
    __syncthreads();
    if (tid < 8) {
        float s = red[tid];
#pragma unroll
        for (int o = 4; o > 0; o >>= 1) s += __shfl_down_sync(0xffu, s, o);
        if (tid == 0) out[b] = s + bfc[0];
    }
}

// =====================================================================================
extern "C" void kernel_launch(void* const* d_in, const int* in_sizes, int n_in,
                              void* d_out, int out_size)
{
    const float* x     = (const float*)d_in[0];
    const float* W_ih0 = (const float*)d_in[1];
    const float* W_hh0 = (const float*)d_in[2];
    const float* b_ih0 = (const float*)d_in[3];
    const float* b_hh0 = (const float*)d_in[4];
    const float* W_ih1 = (const float*)d_in[5];
    const float* W_hh1 = (const float*)d_in[6];
    const float* b_ih1 = (const float*)d_in[7];
    const float* b_hh1 = (const float*)d_in[8];
    const float* W_fc  = (const float*)d_in[9];
    const float* b_fc  = (const float*)d_in[10];
    float* out = (float*)d_out;

    float *xp, *h1, *h2l;
    cudaGetSymbolAddress((void**)&xp,  g_xp);
    cudaGetSymbolAddress((void**)&h1,  g_h1);
    cudaGetSymbolAddress((void**)&h2l, g_h2last);

    dim3 ggemm(M_ / 128, H_ / 128);

    // Phase A: xp0 = x @ W_ih0^T + b_ih0 + b_hh0
    gemm_bias_kernel<<<ggemm, 256>>>(x, W_ih0, b_ih0, b_hh0, xp, IN_);
    // Phase B: layer-0 recurrence, 2 pipelined rows per pair (32 pairs = 64 CTAs)
    rnn_rec2r<true><<<64, 256>>>(xp, W_hh0, h1);
    // Phase C: xp1 = h1 @ W_ih1^T + b_ih1 + b_hh1
    gemm_bias_kernel<<<ggemm, 256>>>(h1, W_ih1, b_ih1, b_hh1, xp, H_);
    // Phase D: layer-1 recurrence, same structure, writes only h2[T-1]
    rnn_rec2r<false><<<64, 256>>>(xp, W_hh1, h2l);
    // Phase E: final projection
    fc_kernel<<<B_, H_>>>(h2l, W_fc, b_fc, out);
}

// round 14
// speedup vs baseline: 1.5584x; 1.5584x over previous
#include <cuda_runtime.h>
#include <math.h>

#define B_  64
#define T_  2048
#define IN_ 128
#define H_  256
#define M_  (B_ * T_)

typedef unsigned long long ull;

// ---------------- scratch ----------------
__device__ float g_xp[(size_t)B_ * T_ * H_];    // reused for xp0 then xp1
__device__ float g_h1[(size_t)B_ * T_ * H_];    // layer-0 hidden states
__device__ float g_h2last[(size_t)B_ * H_];     // h2[:, T-1, :]

// ---------------- packed fp32x2 helpers ----------------
__device__ __forceinline__ void fma2(ull &d, ull a, ull b) {
    asm("fma.rn.f32x2 %0, %1, %2, %0;" : "+l"(d) : "l"(a), "l"(b));
}
__device__ __forceinline__ ull splat2(float x) {
    ull r; asm("mov.b64 %0, {%1, %1};" : "=l"(r) : "f"(x)); return r;
}
__device__ __forceinline__ ull pack2(float a, float b) {
    ull r; asm("mov.b64 %0, {%1, %2};" : "=l"(r) : "r"(__float_as_uint(a)), "r"(__float_as_uint(b)));
    return r;
}
__device__ __forceinline__ float lo2(ull v) { return __uint_as_float((unsigned)(v & 0xffffffffULL)); }
__device__ __forceinline__ float hi2(ull v) { return __uint_as_float((unsigned)(v >> 32)); }

__device__ __forceinline__ float tanh_fast(float s) {
    s = fminf(fmaxf(s, -15.f), 15.f);
    float e; asm("ex2.approx.f32 %0, %1;" : "=f"(e) : "f"(s * 2.885390082f));
    float r; asm("rcp.approx.f32 %0, %1;" : "=f"(r) : "f"(e + 1.f));
    return fmaf(-2.f, r, 1.f);
}

// ---------------- cluster / mbarrier helpers (rec3-proven) ----------------
__device__ __forceinline__ unsigned su32(const void* p) {
    return (unsigned)__cvta_generic_to_shared(p);
}
__device__ __forceinline__ unsigned cta_rank() {
    unsigned r; asm("mov.u32 %0, %%cluster_ctarank;" : "=r"(r)); return r;
}
__device__ __forceinline__ unsigned mapa_u32(unsigned addr, unsigned rank) {
    unsigned r; asm("mapa.shared::cluster.u32 %0, %1, %2;" : "=r"(r) : "r"(addr), "r"(rank));
    return r;
}
__device__ __forceinline__ void mbar_init(unsigned addr, unsigned cnt) {
    asm volatile("mbarrier.init.shared.b64 [%0], %1;" :: "r"(addr), "r"(cnt) : "memory");
}
__device__ __forceinline__ void mbar_expect_tx(unsigned addr, unsigned bytes) {
    asm volatile("mbarrier.arrive.expect_tx.shared.b64 _, [%0], %1;" :: "r"(addr), "r"(bytes) : "memory");
}
__device__ __forceinline__ void mbar_wait_cluster(unsigned addr, unsigned parity) {
    asm volatile(
        "{\n\t.reg .pred P;\n\t"
        "WL_%=:\n\t"
        "mbarrier.try_wait.parity.acquire.cluster.shared::cta.b64 P, [%0], %1, 0x989680;\n\t"
        "@P bra.uni WD_%=;\n\t"
        "bra.uni WL_%=;\n\t"
        "WD_%=:\n\t}"
        :: "r"(addr), "r"(parity) : "memory");
}
__device__ __forceinline__ void st_async_b64(unsigned raddr, ull v, unsigned rmbar) {
    asm volatile(
        "st.async.shared::cluster.mbarrier::complete_tx::bytes.b64 [%0], %1, [%2];"
        :: "r"(raddr), "l"(v), "r"(rmbar) : "memory");
}
__device__ __forceinline__ void cluster_sync_() {
    asm volatile("barrier.cluster.arrive.aligned;" ::: "memory");
    asm volatile("barrier.cluster.wait.aligned;" ::: "memory");
}

// =====================================================================================
// Phase A / C GEMM (proven): C = A @ W^T + bias0 + bias1
// =====================================================================================
__global__ __launch_bounds__(256, 2)
void gemm_bias_kernel(const float* __restrict__ A, const float* __restrict__ W,
                      const float* __restrict__ bias0, const float* __restrict__ bias1,
                      float* __restrict__ C, int K)
{
    __shared__ float a_sm[16][132];
    __shared__ float b_sm[16][132];
    const int tid = threadIdx.x;
    const int tx = tid & 15, ty = tid >> 4;
    const int mBase = blockIdx.x * 128, nBase = blockIdx.y * 128;

    ull acc[8][4];
#pragma unroll
    for (int i = 0; i < 8; i++)
#pragma unroll
        for (int j = 0; j < 4; j++) acc[i][j] = 0ULL;

    for (int kt = 0; kt < K; kt += 16) {
#pragma unroll
        for (int l = 0; l < 2; l++) {
            int idx = l * 256 + tid, row = idx >> 2, kq = idx & 3;
            float4 v = *(const float4*)(A + (size_t)(mBase + row) * K + kt + kq * 4);
            a_sm[kq * 4 + 0][row] = v.x; a_sm[kq * 4 + 1][row] = v.y;
            a_sm[kq * 4 + 2][row] = v.z; a_sm[kq * 4 + 3][row] = v.w;
        }
#pragma unroll
        for (int l = 0; l < 2; l++) {
            int idx = l * 256 + tid, row = idx >> 2, kq = idx & 3;
            float4 v = *(const float4*)(W + (size_t)(nBase + row) * K + kt + kq * 4);
            b_sm[kq * 4 + 0][row] = v.x; b_sm[kq * 4 + 1][row] = v.y;
            b_sm[kq * 4 + 2][row] = v.z; b_sm[kq * 4 + 3][row] = v.w;
        }
        __syncthreads();
#pragma unroll
        for (int kk = 0; kk < 16; kk++) {
            float4 a0 = *(const float4*)&a_sm[kk][ty * 8];
            float4 a1 = *(const float4*)&a_sm[kk][ty * 8 + 4];
            ulonglong2 b0 = *(const ulonglong2*)&b_sm[kk][tx * 8];
            ulonglong2 b1 = *(const ulonglong2*)&b_sm[kk][tx * 8 + 4];
            float av[8] = {a0.x, a0.y, a0.z, a0.w, a1.x, a1.y, a1.z, a1.w};
#pragma unroll
            for (int i = 0; i < 8; i++) {
                ull s = splat2(av[i]);
                fma2(acc[i][0], s, b0.x); fma2(acc[i][1], s, b0.y);
                fma2(acc[i][2], s, b1.x); fma2(acc[i][3], s, b1.y);
            }
        }
        __syncthreads();
    }
    const int n0 = nBase + tx * 8;
    float bj[8];
#pragma unroll
    for (int j = 0; j < 8; j++) bj[j] = bias0[n0 + j] + bias1[n0 + j];
#pragma unroll
    for (int i = 0; i < 8; i++) {
        int m = mBase + ty * 8 + i;
        float4 o0, o1;
        o0.x = lo2(acc[i][0]) + bj[0]; o0.y = hi2(acc[i][0]) + bj[1];
        o0.z = lo2(acc[i][1]) + bj[2]; o0.w = hi2(acc[i][1]) + bj[3];
        o1.x = lo2(acc[i][2]) + bj[4]; o1.y = hi2(acc[i][2]) + bj[5];
        o1.z = lo2(acc[i][3]) + bj[6]; o1.w = hi2(acc[i][3]) + bj[7];
        *(float4*)(C + (size_t)m * H_ + n0)     = o0;
        *(float4*)(C + (size_t)m * H_ + n0 + 4) = o1;
    }
}

// =====================================================================================
// Recurrence v7: 64 clusters x 2 CTAs, 1 row/cluster. rec3 protocol, NEW matvec map:
// thread (og=tid>>3, kc=tid&7) computes 4 outputs {og*4..og*4+3} over k-chunk kc
// (32 k). Chunks 0-3 = own k-half, 4-7 = peer k-half; h stored padded (36 fl/chunk)
// so the 8 distinct per-warp LDS addresses are bank-disjoint (1 wavefront).
// LDS per thread: 8 (was 32). Reduction: 3-level shfl tree over the 8-lane k group.
// Epilogue lane (kc==0): float4 STS/STG + 2x st.async.b64 (512B tx per phase, same
// mbar slots/parity/arm order as rec3).
// =====================================================================================
template<bool STORE_ALL>
__global__ void __cluster_dims__(2, 1, 1) __launch_bounds__(256, 1)
rnn_rec7(const float* __restrict__ xp, const float* __restrict__ Whh,
         float* __restrict__ hout)
{
    __shared__ __align__(16) float h_sm[2][288];   // [buf][8 chunks * 36 floats]
    __shared__ __align__(8)  ull mbar[2];

    const int tid = threadIdx.x;
    const unsigned rank = cta_rank();
    const unsigned peer = rank ^ 1u;
    const int b = blockIdx.x >> 1;
    const int kc = tid & 7;                         // k-chunk 0..7
    const int og = tid >> 3;                        // output group 0..31
    const int o0 = og * 4;                          // first of 4 outputs
    const int o0_glob = (int)rank * 128 + o0;
    const int kbase = (kc < 4) ? ((int)rank * 128 + kc * 32)
                               : ((int)peer * 128 + (kc - 4) * 32);

    // ---- weights: 4 outputs x 32 k = 128 floats (64 ull) ----
    ull wq[4][16];
#pragma unroll
    for (int i = 0; i < 4; ++i) {
        const ulonglong2* src = (const ulonglong2*)(Whh + (size_t)(o0_glob + i) * H_ + kbase);
#pragma unroll
        for (int j = 0; j < 8; ++j) {
            ulonglong2 v = src[j];
            wq[i][2 * j] = v.x; wq[i][2 * j + 1] = v.y;
        }
    }

    // ---- init ----
    if (tid == 0) { mbar_init(su32(&mbar[0]), 1); mbar_init(su32(&mbar[1]), 1); }
    for (int i = tid; i < 2 * 288; i += 256) ((float*)h_sm)[i] = 0.f;   // h[-1] = 0
    __syncthreads();
    cluster_sync_();

    const unsigned my_mbar   = su32(&mbar[0]);
    const unsigned peer_mbar = mapa_u32(my_mbar, peer);
    const unsigned peer_h    = mapa_u32(su32(&h_sm[0][0]), peer);

    const bool epi = (kc == 0);
    const int chunk = og >> 3;                      // own chunk of these outputs
    const int coff  = (og & 7) * 4;                 // offset within chunk
    const size_t xrow = ((size_t)b * T_) * H_ + o0_glob;

    float4 xv = make_float4(0.f, 0.f, 0.f, 0.f);
    if (epi) xv = __ldg((const float4*)(xp + xrow));

    for (int t = 0; t < T_; ++t) {
        const int cb = t & 1, nb = cb ^ 1;

        // prefetch xp[t+1] (hidden under wait + matvec)
        float4 xvn = make_float4(0.f, 0.f, 0.f, 0.f);
        if (epi && t + 1 < T_)
            xvn = __ldg((const float4*)(xp + xrow + (size_t)(t + 1) * H_));

        if (t > 0)
            mbar_wait_cluster(my_mbar + (unsigned)nb * 8u, (unsigned)((t - 1) >> 1) & 1u);
        if (tid == 0) mbar_expect_tx(my_mbar + (unsigned)cb * 8u, 512u);

        // ---- matvec: 4 outputs over this thread's 32-k chunk (8 LDS.128) ----
        const float* hb = &h_sm[cb][kc * 36];
        ull a0 = 0, a1 = 0, a2 = 0, a3 = 0;
#pragma unroll
        for (int j = 0; j < 8; ++j) {
            ulonglong2 hv = *(const ulonglong2*)(hb + j * 4);
            fma2(a0, hv.x, wq[0][2 * j]); fma2(a0, hv.y, wq[0][2 * j + 1]);
            fma2(a1, hv.x, wq[1][2 * j]); fma2(a1, hv.y, wq[1][2 * j + 1]);
            fma2(a2, hv.x, wq[2][2 * j]); fma2(a2, hv.y, wq[2][2 * j + 1]);
            fma2(a3, hv.x, wq[3][2 * j]); fma2(a3, hv.y, wq[3][2 * j + 1]);
        }
        float p0 = lo2(a0) + hi2(a0);
        float p1 = lo2(a1) + hi2(a1);
        float p2 = lo2(a2) + hi2(a2);
        float p3 = lo2(a3) + hi2(a3);

        // reduce across the 8-lane k group (lanes og*8 .. og*8+7)
#pragma unroll
        for (int off = 4; off > 0; off >>= 1) {
            p0 += __shfl_down_sync(0xffffffffu, p0, off);
            p1 += __shfl_down_sync(0xffffffffu, p1, off);
            p2 += __shfl_down_sync(0xffffffffu, p2, off);
            p3 += __shfl_down_sync(0xffffffffu, p3, off);
        }

        if (epi) {
            float h0 = tanh_fast(xv.x + p0);
            float h1v = tanh_fast(xv.y + p1);
            float h2v = tanh_fast(xv.z + p2);
            float h3 = tanh_fast(xv.w + p3);
            // own copy (chunks 0-3)
            *(float4*)&h_sm[nb][chunk * 36 + coff] = make_float4(h0, h1v, h2v, h3);
            // peer copy (their chunks 4-7) + tx
            unsigned paddr = peer_h + (unsigned)(nb * 288 + (chunk + 4) * 36 + coff) * 4u;
            st_async_b64(paddr,      pack2(h0, h1v), peer_mbar + (unsigned)cb * 8u);
            st_async_b64(paddr + 8u, pack2(h2v, h3), peer_mbar + (unsigned)cb * 8u);
            if (STORE_ALL)
                *(float4*)(hout + xrow + (size_t)t * H_) = make_float4(h0, h1v, h2v, h3);
            else if (t == T_ - 1)
                *(float4*)(hout + (size_t)b * H_ + o0_glob) = make_float4(h0, h1v, h2v, h3);
        }
        __syncthreads();
        xv = xvn;
    }

    // drain final incoming phase before any CTA exits
    mbar_wait_cluster(my_mbar + (unsigned)((T_ - 1) & 1) * 8u,
                      (unsigned)((T_ - 1) >> 1) & 1u);
    cluster_sync_();
}

// =====================================================================================
// Final FC
// =====================================================================================
__global__ void fc_kernel(const float* __restrict__ h2l, const float* __restrict__ Wfc,
                          const float* __restrict__ bfc, float* __restrict__ out)
{
    __shared__ float red[8];
    int b = blockIdx.x, tid = threadIdx.x;
    float v = h2l[(size_t)b * H_ + tid] * Wfc[tid];
#pragma unroll
    for (int o = 16; o > 0; o >>= 1) v += __shfl_down_sync(0xffffffffu, v, o);
    if ((tid & 31) == 0) red[tid >> 5] = v;
    __syncthreads();
    if (tid < 8) {
        float s = red[tid];
#pragma unroll
        for (int o = 4; o > 0; o >>= 1) s += __shfl_down_sync(0xffu, s, o);
        if (tid == 0) out[b] = s + bfc[0];
    }
}

// =====================================================================================
extern "C" void kernel_launch(void* const* d_in, const int* in_sizes, int n_in,
                              void* d_out, int out_size)
{
    const float* x     = (const float*)d_in[0];
    const float* W_ih0 = (const float*)d_in[1];
    const float* W_hh0 = (const float*)d_in[2];
    const float* b_ih0 = (const float*)d_in[3];
    const float* b_hh0 = (const float*)d_in[4];
    const float* W_ih1 = (const float*)d_in[5];
    const float* W_hh1 = (const float*)d_in[6];
    const float* b_ih1 = (const float*)d_in[7];
    const float* b_hh1 = (const float*)d_in[8];
    const float* W_fc  = (const float*)d_in[9];
    const float* b_fc  = (const float*)d_in[10];
    float* out = (float*)d_out;

    float *xp, *h1, *h2l;
    cudaGetSymbolAddress((void**)&xp,  g_xp);
    cudaGetSymbolAddress((void**)&h1,  g_h1);
    cudaGetSymbolAddress((void**)&h2l, g_h2last);

    dim3 ggemm(M_ / 128, H_ / 128);

    // Phase A: xp0 = x @ W_ih0^T + b_ih0 + b_hh0
    gemm_bias_kernel<<<ggemm, 256>>>(x, W_ih0, b_ih0, b_hh0, xp, IN_);
    // Phase B: layer-0 recurrence (new 4-output matvec mapping)
    rnn_rec7<true><<<128, 256>>>(xp, W_hh0, h1);
    // Phase C: xp1 = h1 @ W_ih1^T + b_ih1 + b_hh1
    gemm_bias_kernel<<<ggemm, 256>>>(h1, W_ih1, b_ih1, b_hh1, xp, H_);
    // Phase D: layer-1 recurrence, writes only h2[T-1]
    rnn_rec7<false><<<128, 256>>>(xp, W_hh1, h2l);
    // Phase E: final projection
    fc_kernel<<<B_, H_>>>(h2l, W_fc, b_fc, out);
}